// round 13
// baseline (speedup 1.0000x reference)
#include <cuda_runtime.h>
#include <cstdint>

// PolynomialFeatures: out[b] = concat(x[b], x[b, idx_a] * x[b, idx_b])
// x: [B, 256] fp32, out: [B, 256+32640] fp32.
//
// v9 = v8 (ROWS=4, analytic indices, feature-major float4 smem, STG.128) +
//  - __stcs streaming stores: output is write-once/read-never; evict-first
//    keeps the 539MB store stream from thrashing L2 and improves DRAM drain.
//  - __launch_bounds__(256, 8): regs==32 exactly -> 8 blocks/SM, 64 warps
//    resident, max outstanding stores.
//  - quad fast path: ~97% of float4 groups sit inside one run -> single
//    broadcast 'a' load (5 LDS.128 instead of 8) and no boundary loops.

#define ROWS_PER_BLOCK 4
#define F_FEAT 256
#define THREADS 256
#define NPAIRS_EXPECTED 32640   // 256*255/2
#define NGROUPS 8160            // 32640 / 4

__device__ __forceinline__ int pbase(int i) {
    // start of run i: 255*i - i*(i-1)/2
    return i * 255 - ((i * (i - 1)) >> 1);
}
// interleave: consecutive-by-4 features land in adjacent float4 slots
__device__ __forceinline__ int il(int j) {
    return (j >> 2) + (j & 3) * 64;
}

__global__ __launch_bounds__(THREADS, 8)
void poly_features_v9(const float* __restrict__ x,
                      float*       __restrict__ out,
                      int B)
{
    __shared__ float4 sx4[F_FEAT];   // sx4[il(j)] = {row0..row3} of feature j

    const int row0 = blockIdx.x * ROWS_PER_BLOCK;
    const int t    = threadIdx.x;
    const size_t ostride = (size_t)(F_FEAT + NPAIRS_EXPECTED);
    const int rows_here = min(ROWS_PER_BLOCK, B - row0);
    const bool full = (rows_here == ROWS_PER_BLOCK);

    // Stage feature t for the 4 rows; copy x -> out[:, :F] (streaming).
    {
        float v0 = 0.f, v1 = 0.f, v2 = 0.f, v3 = 0.f;
        v0 = x[(size_t)(row0 + 0) * F_FEAT + t];
        __stcs(&out[(size_t)(row0 + 0) * ostride + t], v0);
        if (rows_here > 1) { v1 = x[(size_t)(row0 + 1) * F_FEAT + t];
                             __stcs(&out[(size_t)(row0 + 1) * ostride + t], v1); }
        if (rows_here > 2) { v2 = x[(size_t)(row0 + 2) * F_FEAT + t];
                             __stcs(&out[(size_t)(row0 + 2) * ostride + t], v2); }
        if (rows_here > 3) { v3 = x[(size_t)(row0 + 3) * F_FEAT + t];
                             __stcs(&out[(size_t)(row0 + 3) * ostride + t], v3); }
        sx4[il(t)] = make_float4(v0, v1, v2, v3);
    }
    __syncthreads();

    float* ob0 = out + (size_t)(row0 + 0) * ostride + F_FEAT;
    float* ob1 = out + (size_t)(row0 + 1) * ostride + F_FEAT;
    float* ob2 = out + (size_t)(row0 + 2) * ostride + F_FEAT;
    float* ob3 = out + (size_t)(row0 + 3) * ostride + F_FEAT;

    for (int g = t; g < NGROUPS; g += THREADS) {
        const int p = g << 2;

        // Run index guess + exact fixups, carrying run bounds incrementally.
        int i = (int)((511.0f - sqrtf((float)(261121 - 8 * p))) * 0.5f);
        i = max(0, min(i, 254));
        int bi  = pbase(i);          // start of run i
        int bi1 = bi + (255 - i);    // start of run i+1
        while (bi1 <= p) { ++i; bi = bi1; bi1 += 255 - i; }
        while (i > 0 && bi > p) { bi1 = bi; --i; bi -= 255 - i; }

        float4 v0, v1, v2, v3;

        if (p + 3 < bi1) {
            // FAST PATH (~97%): whole quad inside run i -> one broadcast 'a'.
            const int j0 = p - bi + i + 1;
            const float4 a  = sx4[il(i)];
            const float4 b0 = sx4[il(j0 + 0)];
            const float4 b1 = sx4[il(j0 + 1)];
            const float4 b2 = sx4[il(j0 + 2)];
            const float4 b3 = sx4[il(j0 + 3)];
            v0 = make_float4(a.x*b0.x, a.x*b1.x, a.x*b2.x, a.x*b3.x);
            v1 = make_float4(a.y*b0.y, a.y*b1.y, a.y*b2.y, a.y*b3.y);
            v2 = make_float4(a.z*b0.z, a.z*b1.z, a.z*b2.z, a.z*b3.z);
            v3 = make_float4(a.w*b0.w, a.w*b1.w, a.w*b2.w, a.w*b3.w);
        } else {
            // SLOW PATH: quad crosses a run boundary.
            #pragma unroll
            for (int e = 0; e < 4; e++) {
                const int pe = p + e;
                while (pe >= bi1) { ++i; bi = bi1; bi1 += 255 - i; }
                const int j = pe - bi + i + 1;
                const float4 a = sx4[il(i)];
                const float4 b = sx4[il(j)];
                ((float*)&v0)[e] = a.x * b.x;
                ((float*)&v1)[e] = a.y * b.y;
                ((float*)&v2)[e] = a.z * b.z;
                ((float*)&v3)[e] = a.w * b.w;
            }
        }

        __stcs((float4*)(ob0 + p), v0);
        if (full) {
            __stcs((float4*)(ob1 + p), v1);
            __stcs((float4*)(ob2 + p), v2);
            __stcs((float4*)(ob3 + p), v3);
        } else {
            if (rows_here > 1) __stcs((float4*)(ob1 + p), v1);
            if (rows_here > 2) __stcs((float4*)(ob2 + p), v2);
        }
    }
}

// ---- Generic fallback (idx-driven), used only if npairs != 32640 ----
__global__ __launch_bounds__(THREADS)
void poly_features_generic(const float* __restrict__ x,
                           const int*   __restrict__ idx_a,
                           const int*   __restrict__ idx_b,
                           float*       __restrict__ out,
                           int B, int npairs)
{
    __shared__ float sxl[ROWS_PER_BLOCK][F_FEAT];
    const int row0 = blockIdx.x * ROWS_PER_BLOCK;
    const int tid  = threadIdx.x;
    const size_t out_stride = (size_t)(F_FEAT + npairs);

    #pragma unroll
    for (int r = 0; r < ROWS_PER_BLOCK; r++) {
        int row = row0 + r;
        if (row < B) {
            float v = x[(size_t)row * F_FEAT + tid];
            sxl[r][tid] = v;
            out[(size_t)row * out_stride + tid] = v;
        }
    }
    __syncthreads();

    const int rows_here = min(ROWS_PER_BLOCK, B - row0);
    for (int p = tid; p < npairs; p += THREADS) {
        int ai = idx_a[p];
        int bi = idx_b[p];
        #pragma unroll
        for (int r = 0; r < ROWS_PER_BLOCK; r++) {
            if (r < rows_here)
                out[(size_t)(row0 + r) * out_stride + F_FEAT + p] = sxl[r][ai] * sxl[r][bi];
        }
    }
}

extern "C" void kernel_launch(void* const* d_in, const int* in_sizes, int n_in,
                              void* d_out, int out_size)
{
    const float* x     = (const float*)d_in[0];
    const int*   idx_a = (const int*)d_in[1];
    const int*   idx_b = (const int*)d_in[2];
    float*       out   = (float*)d_out;

    const int B = in_sizes[0] / F_FEAT;
    const int npairs = in_sizes[1];
    const int grid = (B + ROWS_PER_BLOCK - 1) / ROWS_PER_BLOCK;

    if (npairs == NPAIRS_EXPECTED) {
        poly_features_v9<<<grid, THREADS>>>(x, out, B);
    } else {
        poly_features_generic<<<grid, THREADS>>>(x, idx_a, idx_b, out, B, npairs);
    }
}